// round 9
// baseline (speedup 1.0000x reference)
#include <cuda_runtime.h>
#include <cuda_fp16.h>
#include <cstdint>
#include <math.h>

#define HH 128
#define WW 128
#define HW 16384
#define CC 16
#define NPTS 32
#define NLINES (5 * HW)
#define LOI_FLOATS (NLINES * (CC * NPTS))   // 41,943,040
#define J_OFF LOI_FLOATS
#define S_OFF (LOI_FLOATS + 600)
#define TOPK 300
#define NSEG 128
#define SEGSTRIDE 136                        // 128 keys + 8 pad, 16B-aligned
#define NTILEB 1024                          // 32x32 tiles of 4x4 px

// ---- device scratch ----
__device__ uint4 g_fthv[HW * 2];             // features fp16 (H,W,C): 32B/pixel
__device__ float4 g_geom[NLINES];            // per-line (ux,uy,vx,vy)
__device__ unsigned long long g_keys[NSEG * SEGSTRIDE];
__device__ int g_bcnt[NSEG];

// ---- packed f32x2 helpers ----
__device__ __forceinline__ unsigned long long pk2(float lo, float hi) {
    unsigned long long r;
    asm("mov.b64 %0, {%1, %2};" : "=l"(r) : "f"(lo), "f"(hi));
    return r;
}
__device__ __forceinline__ unsigned long long mul2(unsigned long long a, unsigned long long b) {
    unsigned long long d;
    asm("mul.rn.f32x2 %0, %1, %2;" : "=l"(d) : "l"(a), "l"(b));
    return d;
}
__device__ __forceinline__ unsigned long long fma2(unsigned long long a, unsigned long long b,
                                                   unsigned long long c) {
    unsigned long long d;
    asm("fma.rn.f32x2 %0, %1, %2, %3;" : "=l"(d) : "l"(a), "l"(b), "l"(c));
    return d;
}
__device__ __forceinline__ float2 up2(unsigned long long v) {
    float2 r;
    asm("mov.b64 {%0, %1}, %2;" : "=f"(r.x), "=f"(r.y) : "l"(v));
    return r;
}
__device__ __forceinline__ float2 h2f(unsigned u) {
    __half2 h = *reinterpret_cast<const __half2*>(&u);
    return __half22float2(h);
}

// ---------------------------------------------------------------------------
// Kernel 1 (prep): fp16 transpose + geometry + NMS compact. 128 x 128.
// ---------------------------------------------------------------------------
__global__ void __launch_bounds__(128) prep_kernel(
    const float* __restrict__ f,
    const float* __restrict__ md,
    const float* __restrict__ dis,
    const float* __restrict__ res,
    const float* __restrict__ jloc)
{
    __shared__ int s_cnt;
    const int tid = threadIdx.x;
    const int bid = blockIdx.x;
    const int p = bid * 128 + tid;
    if (tid == 0) s_cnt = 0;
    __syncthreads();

    const int yi = p >> 7;
    const int xi = p & 127;

    // transpose + fp16 convert: (C,H,W) f32 -> (H,W,C) fp16
    {
        unsigned h[8];
#pragma unroll
        for (int k = 0; k < 8; k++) {
            float lo = f[(2 * k + 0) * HW + p];
            float hi = f[(2 * k + 1) * HW + p];
            __half2 hh = __floats2half2_rn(lo, hi);
            h[k] = *reinterpret_cast<unsigned*>(&hh);
        }
        g_fthv[p * 2 + 0] = make_uint4(h[0], h[1], h[2], h[3]);
        g_fthv[p * 2 + 1] = make_uint4(h[4], h[5], h[6], h[7]);
    }

    // geometry (exact trig once per pixel)
    const float md0 = md[p];
    const float md1 = md[HW + p];
    const float md2 = md[2 * HW + p];
    const float d0  = dis[p];
    const float rs  = res[p];

    float ss, cs;
    sincosf((md0 - 0.5f) * 6.2831853071795864f, &ss, &cs);
    const float yst = tanf(md1 * 1.5707963267948966f);
    const float yed = tanf(-md2 * 1.5707963267948966f);
    const float ax = cs - ss * yst, ay = ss + cs * yst;
    const float bx = cs - ss * yed, by = ss + cs * yed;
    const float fx = (float)xi, fy = (float)yi;

#pragma unroll
    for (int r = 0; r < 5; r++) {
        float dval = fminf(fmaxf(d0 + rs * (float)(r - 2), 0.0f), 1.0f);
        const float ds = dval * 5.0f;
        float4 g;
        g.x = fminf(fmaxf(ax * ds + fx, 0.0f), 127.0f);
        g.y = fminf(fmaxf(ay * ds + fy, 0.0f), 127.0f);
        g.z = fminf(fmaxf(bx * ds + fx, 0.0f), 127.0f);
        g.w = fminf(fmaxf(by * ds + fy, 0.0f), 127.0f);
        g_geom[r * HW + p] = g;
    }

    // 3x3 NMS + per-block compaction
    float a = jloc[p];
    float m = -INFINITY;
#pragma unroll
    for (int dy = -1; dy <= 1; dy++) {
#pragma unroll
        for (int dx = -1; dx <= 1; dx++) {
            int yy = yi + dy, xx = xi + dx;
            if (yy >= 0 && yy < HH && xx >= 0 && xx < WW)
                m = fmaxf(m, jloc[yy * WW + xx]);
        }
    }
    if (a == m && a > 0.0f) {
        int pos = atomicAdd(&s_cnt, 1);
        g_keys[bid * SEGSTRIDE + pos] =
            ((unsigned long long)__float_as_uint(a) << 32) |
            (unsigned long long)(0xFFFFFFFFu - (unsigned)p);
    }
    __syncthreads();
    int c0 = s_cnt;
    if (tid >= c0 && tid < c0 + 8)            // zero-pad for blind ull2 reads
        g_keys[bid * SEGSTRIDE + tid] = 0ULL;
    if (tid == 0) g_bcnt[bid] = c0;
}

// ---------------------------------------------------------------------------
// Kernel 2 (topk): rank-by-counting over padded global segments.
// ---------------------------------------------------------------------------
__global__ void __launch_bounds__(256) topk_kernel(
    const float* __restrict__ joff, float* __restrict__ out)
{
    __shared__ int s_bc[NSEG];
    __shared__ int s_ps[NSEG + 1];
    const int tid = threadIdx.x;

    if (tid < NSEG) s_bc[tid] = g_bcnt[tid];
    __syncthreads();
    if (tid == 0) {
        int acc = 0;
#pragma unroll
        for (int b = 0; b < NSEG; b++) { s_ps[b] = acc; acc += s_bc[b]; }
        s_ps[NSEG] = acc;
    }
    __syncthreads();

    const int cnt = s_ps[NSEG];
    const int gid = blockIdx.x * 256 + tid;
    if (gid >= cnt) return;

    int lo = 0, hi = NSEG - 1;
    while (lo < hi) {
        int mid = (lo + hi + 1) >> 1;
        if (s_ps[mid] <= gid) lo = mid; else hi = mid - 1;
    }
    const unsigned long long mykey = g_keys[lo * SEGSTRIDE + (gid - s_ps[lo])];

    int rank = 0;
#pragma unroll 1
    for (int b = 0; b < NSEG; b++) {
        const int n2 = (s_bc[b] + 1) >> 1;
        const ulonglong2* kp = (const ulonglong2*)(g_keys + b * SEGSTRIDE);
#pragma unroll 4
        for (int i = 0; i < n2; i++) {
            ulonglong2 v = kp[i];
            rank += (v.x > mykey) + (v.y > mykey);
        }
    }

    if (rank < TOPK) {
        unsigned idx = 0xFFFFFFFFu - (unsigned)(mykey & 0xFFFFFFFFull);
        float val = __uint_as_float((unsigned)(mykey >> 32));
        float fy = (float)(idx >> 7);
        float fx = (float)(idx & 127);
        out[J_OFF + 2 * rank + 0] = fx + joff[idx] + 0.5f;
        out[J_OFF + 2 * rank + 1] = fy + joff[HW + idx] + 0.5f;
        out[S_OFF + rank] = val;
    }
}

// ---------------------------------------------------------------------------
// Kernel 3 (loi): classic launch, block = 4x4-pixel tile (L1 locality),
// manual 2-stage software pipeline so gathers for iter n+1 are in flight
// while iter n is consumed. 128-reg budget (2 blocks/SM).
// ---------------------------------------------------------------------------
__global__ void __launch_bounds__(256, 2) loi_kernel(float* __restrict__ out)
{
    const int warp = threadIdx.x >> 5;
    const int lane = threadIdx.x & 31;
    const int tx = blockIdx.x & 31;
    const int ty = blockIdx.x >> 5;
    const float t   = (float)lane * (1.0f / 31.0f);
    const float omt = 1.0f - t;

    unsigned buf[2][32];        // gathered fp16x2: [slot][c00:0-7|c10:8-15|c01:16-23|c11:24-31]
    float4   wbuf[2];
    int      lbuf[2];

#define STAGE(IT, S)                                                           \
    {                                                                          \
        const int i   = (IT) * 8 + warp;                                       \
        const int pix = i / 5;                                                 \
        const int r   = i - pix * 5;                                           \
        const int p   = ((ty * 4 + (pix >> 2)) << 7) + tx * 4 + (pix & 3);     \
        const int l   = r * HW + p;                                            \
        lbuf[S] = l;                                                           \
        const float4 g = g_geom[l];                                            \
        const float px = g.x * t + g.z * omt - 0.5f;                           \
        const float py = g.y * t + g.w * omt - 0.5f;                           \
        const float px0 = fminf(fmaxf(floorf(px), 0.0f), 127.0f);              \
        const float py0 = fminf(fmaxf(floorf(py), 0.0f), 127.0f);              \
        const float px1 = fminf(px0 + 1.0f, 127.0f);                           \
        const float py1 = fminf(py0 + 1.0f, 127.0f);                           \
        const int ix0 = (int)px0, iy0 = (int)py0;                              \
        const int ix1 = (int)px1, iy1 = (int)py1;                              \
        wbuf[S] = make_float4((py1 - py) * (px1 - px), (py - py0) * (px1 - px),\
                              (py1 - py) * (px - px0), (py - py0) * (px - px0));\
        const int o00 = (iy0 * WW + ix0) * 2;                                  \
        const int o10 = (iy1 * WW + ix0) * 2;                                  \
        const int o01 = (iy0 * WW + ix1) * 2;                                  \
        const int o11 = (iy1 * WW + ix1) * 2;                                  \
        uint4 v;                                                               \
        v = g_fthv[o00];     buf[S][0]=v.x;  buf[S][1]=v.y;  buf[S][2]=v.z;  buf[S][3]=v.w;   \
        v = g_fthv[o00 + 1]; buf[S][4]=v.x;  buf[S][5]=v.y;  buf[S][6]=v.z;  buf[S][7]=v.w;   \
        v = g_fthv[o10];     buf[S][8]=v.x;  buf[S][9]=v.y;  buf[S][10]=v.z; buf[S][11]=v.w;  \
        v = g_fthv[o10 + 1]; buf[S][12]=v.x; buf[S][13]=v.y; buf[S][14]=v.z; buf[S][15]=v.w;  \
        v = g_fthv[o01];     buf[S][16]=v.x; buf[S][17]=v.y; buf[S][18]=v.z; buf[S][19]=v.w;  \
        v = g_fthv[o01 + 1]; buf[S][20]=v.x; buf[S][21]=v.y; buf[S][22]=v.z; buf[S][23]=v.w;  \
        v = g_fthv[o11];     buf[S][24]=v.x; buf[S][25]=v.y; buf[S][26]=v.z; buf[S][27]=v.w;  \
        v = g_fthv[o11 + 1]; buf[S][28]=v.x; buf[S][29]=v.y; buf[S][30]=v.z; buf[S][31]=v.w;  \
    }

    STAGE(0, 0);

#pragma unroll 2
    for (int it = 0; it < 10; it++) {
        const int cs = it & 1;
        const int ns = cs ^ 1;
        if (it < 9) { STAGE(it + 1, ns); }

        const float4 w = wbuf[cs];
        const unsigned long long w00 = pk2(w.x, w.x);
        const unsigned long long w10 = pk2(w.y, w.y);
        const unsigned long long w01 = pk2(w.z, w.z);
        const unsigned long long w11 = pk2(w.w, w.w);
        float* __restrict__ o = out + (size_t)lbuf[cs] * (CC * NPTS) + lane;

#pragma unroll
        for (int k = 0; k < 8; k++) {
            float2 fa = h2f(buf[cs][k]);
            float2 fb = h2f(buf[cs][8 + k]);
            float2 fc = h2f(buf[cs][16 + k]);
            float2 fd = h2f(buf[cs][24 + k]);
            unsigned long long acc = mul2(pk2(fa.x, fa.y), w00);
            acc = fma2(pk2(fb.x, fb.y), w10, acc);
            acc = fma2(pk2(fc.x, fc.y), w01, acc);
            acc = fma2(pk2(fd.x, fd.y), w11, acc);
            float2 v = up2(acc);
            __stcs(o + (2 * k + 0) * NPTS, v.x);
            __stcs(o + (2 * k + 1) * NPTS, v.y);
        }
    }
#undef STAGE
}

// ---------------------------------------------------------------------------
extern "C" void kernel_launch(void* const* d_in, const int* in_sizes, int n_in,
                              void* d_out, int out_size) {
    const float* md   = (const float*)d_in[0];
    const float* dis  = (const float*)d_in[1];
    const float* res  = (const float*)d_in[2];
    const float* feat = (const float*)d_in[3];
    const float* jloc = (const float*)d_in[4];
    const float* joff = (const float*)d_in[5];
    float* out = (float*)d_out;

    prep_kernel<<<NSEG, 128>>>(feat, md, dis, res, jloc);
    topk_kernel<<<16, 256>>>(joff, out);
    loi_kernel<<<NTILEB, 256>>>(out);
}